// round 11
// baseline (speedup 1.0000x reference)
#include <cuda_runtime.h>
#include <cuda_fp16.h>
#include <cstdint>

// out[n,d] = sum_k mat[n,k] * feat[graph[n,k], d];  N=100000, K=32, DIM=64.
//   1) convert feat fp32 -> fp16 scratch (12.8MB, L2-resident); 8 elems/thread;
//      fires griddepcontrol.launch_dependents at entry (PDL).
//   2) gather: one user-quad per warp, 128-thread CTAs (grid 6250) for finer
//      wave granularity; LDG.128 of 8 halves; mixed fma.rn.f32.f16.
//      graph/mat preloads run BEFORE griddepcontrol.wait (overlap convert).
// Gather steady-state is at the LTS chip cap (~6300 B/cyc); this round trims
// last-wave tail / CTA spread via smaller CTAs.

#define K_NEIGH 32
#define DIM 64
#define NUSER_MAX 100000
#define FULL 0xffffffffu

__device__ __align__(16) __half g_feat_h[(size_t)NUSER_MAX * DIM];

__global__ void __launch_bounds__(256)
convert_kernel(const float* __restrict__ feat, int total8) {
    // Dependent gather grid may begin launching; its pre-wait phase touches
    // only graph/mat, never g_feat_h.
    asm volatile("griddepcontrol.launch_dependents;");

    const int i = blockIdx.x * blockDim.x + threadIdx.x;
    if (i >= total8) return;
    const float4 a = reinterpret_cast<const float4*>(feat)[2 * i];
    const float4 b = reinterpret_cast<const float4*>(feat)[2 * i + 1];
    __half2 h0 = __floats2half2_rn(a.x, a.y);
    __half2 h1 = __floats2half2_rn(a.z, a.w);
    __half2 h2 = __floats2half2_rn(b.x, b.y);
    __half2 h3 = __floats2half2_rn(b.z, b.w);
    uint4 s;
    s.x = *reinterpret_cast<unsigned int*>(&h0);
    s.y = *reinterpret_cast<unsigned int*>(&h1);
    s.z = *reinterpret_cast<unsigned int*>(&h2);
    s.w = *reinterpret_cast<unsigned int*>(&h3);
    reinterpret_cast<uint4*>(g_feat_h)[i] = s;
}

// fp32 accumulator += fp16 a * fp16 b  (single SASS op on sm_100+)
__device__ __forceinline__ void fma_mixed(float& acc, unsigned short ha, unsigned short hb) {
    asm("fma.rn.f32.f16 %0, %1, %2, %0;" : "+f"(acc) : "h"(ha), "h"(hb));
}

__global__ void __launch_bounds__(128, 12)
user_graph_kernel(const int* __restrict__ graph,
                  const float* __restrict__ mat,
                  float* __restrict__ out,
                  int num_user) {
    const int gtid = blockIdx.x * blockDim.x + threadIdx.x;
    const int warp = gtid >> 5;          // warp id: owns 4 users
    const int lane = gtid & 31;
    const int grp  = lane >> 3;          // which user of the 4
    const int sub  = lane & 7;           // dim-octet within user

    const int u0 = warp * 4;
    if (u0 >= num_user) return;          // num_user divisible by 4 -> whole warp valid

    // ---- Pre-wait phase: reads only graph/mat (independent of convert) ----
    const size_t base = (size_t)(u0 + grp) * K_NEIGH + sub;
    const int offA = graph[base]      << 7;   // idx * 128 B (fp16 row)
    const int offB = graph[base + 8]  << 7;
    const int offC = graph[base + 16] << 7;
    const int offD = graph[base + 24] << 7;
    const int hwA = (int)__half_as_ushort(__float2half_rn(mat[base]));
    const int hwB = (int)__half_as_ushort(__float2half_rn(mat[base + 8]));
    const int hwC = (int)__half_as_ushort(__float2half_rn(mat[base + 16]));
    const int hwD = (int)__half_as_ushort(__float2half_rn(mat[base + 24]));

    float acc[8];
    #pragma unroll
    for (int i = 0; i < 8; ++i) acc[i] = 0.0f;

    const char* fbase = reinterpret_cast<const char*>(g_feat_h) + (size_t)(sub << 4);

    // ---- Wait for the convert kernel's writes to be visible ----
    asm volatile("griddepcontrol.wait;" ::: "memory");

    #pragma unroll
    for (int k = 0; k < K_NEIGH; ++k) {
        const int src = (lane & 24) | (k & 7);
        const int ov = (k < 8) ? offA : (k < 16) ? offB : (k < 24) ? offC : offD;
        const int wv = (k < 8) ? hwA  : (k < 16) ? hwB  : (k < 24) ? hwC  : hwD;
        const int go = __shfl_sync(FULL, ov, src);
        const unsigned short hw = (unsigned short)__shfl_sync(FULL, wv, src);

        // 16B = 8 halves of the gathered row at dims [sub*8 .. sub*8+7]
        const uint4 p = __ldg(reinterpret_cast<const uint4*>(fbase + (size_t)(unsigned)go));
        const __half2 h0 = *reinterpret_cast<const __half2*>(&p.x);
        const __half2 h1 = *reinterpret_cast<const __half2*>(&p.y);
        const __half2 h2 = *reinterpret_cast<const __half2*>(&p.z);
        const __half2 h3 = *reinterpret_cast<const __half2*>(&p.w);

        fma_mixed(acc[0], __half_as_ushort(h0.x), hw);
        fma_mixed(acc[1], __half_as_ushort(h0.y), hw);
        fma_mixed(acc[2], __half_as_ushort(h1.x), hw);
        fma_mixed(acc[3], __half_as_ushort(h1.y), hw);
        fma_mixed(acc[4], __half_as_ushort(h2.x), hw);
        fma_mixed(acc[5], __half_as_ushort(h2.y), hw);
        fma_mixed(acc[6], __half_as_ushort(h3.x), hw);
        fma_mixed(acc[7], __half_as_ushort(h3.y), hw);
    }

    // Lane writes dims [sub*8 .. sub*8+7] of user u0+grp: 2x STG.128.
    float* obase = out + (size_t)(u0 + grp) * DIM + (size_t)(sub << 3);
    *reinterpret_cast<float4*>(obase)     = make_float4(acc[0], acc[1], acc[2], acc[3]);
    *reinterpret_cast<float4*>(obase + 4) = make_float4(acc[4], acc[5], acc[6], acc[7]);
}

extern "C" void kernel_launch(void* const* d_in, const int* in_sizes, int n_in,
                              void* d_out, int out_size) {
    const float* feat  = (const float*)d_in[0];   // [N, 64] float32
    const int*   graph = (const int*)d_in[1];     // [N, 32] int32
    const float* mat   = (const float*)d_in[2];   // [N, 32] float32
    float*       out   = (float*)d_out;           // [N, 64] float32

    const int num_user = in_sizes[0] / DIM;       // 100000

    // Kernel 1: fp32 -> fp16 feature table (8 floats -> one 16B store / thread)
    const int total8 = num_user * DIM / 8;        // 800,000
    convert_kernel<<<(total8 + 255) / 256, 256>>>(feat, total8);

    // Kernel 2: gather + weighted reduce, PDL dependent; 128-thread CTAs.
    const int users_per_block = 16;               // 4 warps * 4 users
    const int blocks = (num_user + users_per_block - 1) / users_per_block;  // 6250

    cudaLaunchConfig_t cfg = {};
    cfg.gridDim  = dim3(blocks, 1, 1);
    cfg.blockDim = dim3(128, 1, 1);
    cfg.dynamicSmemBytes = 0;
    cfg.stream = 0;                               // same (legacy) stream as <<<>>>
    cudaLaunchAttribute attrs[1];
    attrs[0].id = cudaLaunchAttributeProgrammaticStreamSerialization;
    attrs[0].val.programmaticStreamSerializationAllowed = 1;
    cfg.attrs = attrs;
    cfg.numAttrs = 1;

    cudaLaunchKernelEx(&cfg, user_graph_kernel, graph, mat, out, num_user);
}

// round 12
// speedup vs baseline: 1.0010x; 1.0010x over previous
#include <cuda_runtime.h>
#include <cuda_fp16.h>
#include <cstdint>

// FINAL — converged at the LTS chip-cap floor.
// out[n,d] = sum_k mat[n,k] * feat[graph[n,k], d];  N=100000, K=32, DIM=64.
//   1) convert feat fp32 -> fp16 scratch (12.8MB, L2-resident); 8 elems/thread;
//      fires griddepcontrol.launch_dependents at entry (PDL).
//   2) gather: one user-quad per warp, 128-thread CTAs (grid 6250);
//      LDG.128 of 8 halves; mixed fma.rn.f32.f16 (fp32 accumulate).
//      graph/mat preloads run BEFORE griddepcontrol.wait (overlap convert).
// Evidence: gather steady-state 30.3-30.8us across 6 structural variants ->
// pinned at ~6300 B/cyc LTS cap (~15.5 TB/s achieved). fp16 is the smallest
// format passing rel_err < 1e-3 (measured 2.78e-4; bf16/int8 model over-gate).

#define K_NEIGH 32
#define DIM 64
#define NUSER_MAX 100000
#define FULL 0xffffffffu

__device__ __align__(16) __half g_feat_h[(size_t)NUSER_MAX * DIM];

__global__ void __launch_bounds__(256)
convert_kernel(const float* __restrict__ feat, int total8) {
    // Dependent gather grid may begin launching; its pre-wait phase touches
    // only graph/mat, never g_feat_h.
    asm volatile("griddepcontrol.launch_dependents;");

    const int i = blockIdx.x * blockDim.x + threadIdx.x;
    if (i >= total8) return;
    const float4 a = reinterpret_cast<const float4*>(feat)[2 * i];
    const float4 b = reinterpret_cast<const float4*>(feat)[2 * i + 1];
    __half2 h0 = __floats2half2_rn(a.x, a.y);
    __half2 h1 = __floats2half2_rn(a.z, a.w);
    __half2 h2 = __floats2half2_rn(b.x, b.y);
    __half2 h3 = __floats2half2_rn(b.z, b.w);
    uint4 s;
    s.x = *reinterpret_cast<unsigned int*>(&h0);
    s.y = *reinterpret_cast<unsigned int*>(&h1);
    s.z = *reinterpret_cast<unsigned int*>(&h2);
    s.w = *reinterpret_cast<unsigned int*>(&h3);
    reinterpret_cast<uint4*>(g_feat_h)[i] = s;
}

// fp32 accumulator += fp16 a * fp16 b  (single SASS op on sm_100+)
__device__ __forceinline__ void fma_mixed(float& acc, unsigned short ha, unsigned short hb) {
    asm("fma.rn.f32.f16 %0, %1, %2, %0;" : "+f"(acc) : "h"(ha), "h"(hb));
}

__global__ void __launch_bounds__(128, 12)
user_graph_kernel(const int* __restrict__ graph,
                  const float* __restrict__ mat,
                  float* __restrict__ out,
                  int num_user) {
    const int gtid = blockIdx.x * blockDim.x + threadIdx.x;
    const int warp = gtid >> 5;          // warp id: owns 4 users
    const int lane = gtid & 31;
    const int grp  = lane >> 3;          // which user of the 4
    const int sub  = lane & 7;           // dim-octet within user

    const int u0 = warp * 4;
    if (u0 >= num_user) return;          // num_user divisible by 4 -> whole warp valid

    // ---- Pre-wait phase: reads only graph/mat (independent of convert) ----
    const size_t base = (size_t)(u0 + grp) * K_NEIGH + sub;
    const int offA = graph[base]      << 7;   // idx * 128 B (fp16 row)
    const int offB = graph[base + 8]  << 7;
    const int offC = graph[base + 16] << 7;
    const int offD = graph[base + 24] << 7;
    const int hwA = (int)__half_as_ushort(__float2half_rn(mat[base]));
    const int hwB = (int)__half_as_ushort(__float2half_rn(mat[base + 8]));
    const int hwC = (int)__half_as_ushort(__float2half_rn(mat[base + 16]));
    const int hwD = (int)__half_as_ushort(__float2half_rn(mat[base + 24]));

    float acc[8];
    #pragma unroll
    for (int i = 0; i < 8; ++i) acc[i] = 0.0f;

    const char* fbase = reinterpret_cast<const char*>(g_feat_h) + (size_t)(sub << 4);

    // ---- Wait for the convert kernel's writes to be visible ----
    asm volatile("griddepcontrol.wait;" ::: "memory");

    #pragma unroll
    for (int k = 0; k < K_NEIGH; ++k) {
        const int src = (lane & 24) | (k & 7);
        const int ov = (k < 8) ? offA : (k < 16) ? offB : (k < 24) ? offC : offD;
        const int wv = (k < 8) ? hwA  : (k < 16) ? hwB  : (k < 24) ? hwC  : hwD;
        const int go = __shfl_sync(FULL, ov, src);
        const unsigned short hw = (unsigned short)__shfl_sync(FULL, wv, src);

        // 16B = 8 halves of the gathered row at dims [sub*8 .. sub*8+7]
        const uint4 p = __ldg(reinterpret_cast<const uint4*>(fbase + (size_t)(unsigned)go));
        const __half2 h0 = *reinterpret_cast<const __half2*>(&p.x);
        const __half2 h1 = *reinterpret_cast<const __half2*>(&p.y);
        const __half2 h2 = *reinterpret_cast<const __half2*>(&p.z);
        const __half2 h3 = *reinterpret_cast<const __half2*>(&p.w);

        fma_mixed(acc[0], __half_as_ushort(h0.x), hw);
        fma_mixed(acc[1], __half_as_ushort(h0.y), hw);
        fma_mixed(acc[2], __half_as_ushort(h1.x), hw);
        fma_mixed(acc[3], __half_as_ushort(h1.y), hw);
        fma_mixed(acc[4], __half_as_ushort(h2.x), hw);
        fma_mixed(acc[5], __half_as_ushort(h2.y), hw);
        fma_mixed(acc[6], __half_as_ushort(h3.x), hw);
        fma_mixed(acc[7], __half_as_ushort(h3.y), hw);
    }

    // Lane writes dims [sub*8 .. sub*8+7] of user u0+grp: 2x STG.128.
    float* obase = out + (size_t)(u0 + grp) * DIM + (size_t)(sub << 3);
    *reinterpret_cast<float4*>(obase)     = make_float4(acc[0], acc[1], acc[2], acc[3]);
    *reinterpret_cast<float4*>(obase + 4) = make_float4(acc[4], acc[5], acc[6], acc[7]);
}

extern "C" void kernel_launch(void* const* d_in, const int* in_sizes, int n_in,
                              void* d_out, int out_size) {
    const float* feat  = (const float*)d_in[0];   // [N, 64] float32
    const int*   graph = (const int*)d_in[1];     // [N, 32] int32
    const float* mat   = (const float*)d_in[2];   // [N, 32] float32
    float*       out   = (float*)d_out;           // [N, 64] float32

    const int num_user = in_sizes[0] / DIM;       // 100000

    // Kernel 1: fp32 -> fp16 feature table (8 floats -> one 16B store / thread)
    const int total8 = num_user * DIM / 8;        // 800,000
    convert_kernel<<<(total8 + 255) / 256, 256>>>(feat, total8);

    // Kernel 2: gather + weighted reduce, PDL dependent; 128-thread CTAs.
    const int users_per_block = 16;               // 4 warps * 4 users
    const int blocks = (num_user + users_per_block - 1) / users_per_block;  // 6250

    cudaLaunchConfig_t cfg = {};
    cfg.gridDim  = dim3(blocks, 1, 1);
    cfg.blockDim = dim3(128, 1, 1);
    cfg.dynamicSmemBytes = 0;
    cfg.stream = 0;                               // same (legacy) stream as <<<>>>
    cudaLaunchAttribute attrs[1];
    attrs[0].id = cudaLaunchAttributeProgrammaticStreamSerialization;
    attrs[0].val.programmaticStreamSerializationAllowed = 1;
    cfg.attrs = attrs;
    cfg.numAttrs = 1;

    cudaLaunchKernelEx(&cfg, user_graph_kernel, graph, mat, out, num_user);
}